// round 9
// baseline (speedup 1.0000x reference)
#include <cuda_runtime.h>
#include <cstdint>

#define BB 64
#define TT 512
#define DD 768
#define HH 384
#define GG 1536
#define NTAG 30
#define NCTA_LSTM 128

// ---------------- static device scratch (no runtime allocation) --------------
__device__ float g_pre[2u * BB * TT * GG];     // per-layer projections, both dirs
__device__ float g_h1[BB * TT * 2 * HH];       // layer0 output
__device__ float g_h2[BB * TT * 2 * HH];       // layer1 output
__device__ float g_feats[BB * TT * NTAG];      // FC output
__device__ float g_hstate[2 * 2 * HH * BB];    // [buf][dir][j][b] recurrent h
__device__ unsigned int g_barArrive2[2];       // zero-init
__device__ volatile unsigned int g_barEpoch2[2];

// ---------------- packed fp32x2 helpers (Blackwell FFMA2 path) ---------------
__device__ __forceinline__ unsigned long long pack2(float lo, float hi) {
    unsigned long long r;
    asm("mov.b64 %0, {%1, %2};" : "=l"(r) : "f"(lo), "f"(hi));
    return r;
}
__device__ __forceinline__ void ffma2(unsigned long long& d,
                                      unsigned long long a, unsigned long long b) {
    asm("fma.rn.f32x2 %0, %1, %2, %0;" : "+l"(d) : "l"(a), "l"(b));
}
__device__ __forceinline__ float2 unpack2(unsigned long long v) {
    float lo, hi;
    asm("mov.b64 {%0, %1}, %2;" : "=f"(lo), "=f"(hi) : "l"(v));
    return make_float2(lo, hi);
}

// group-local named barrier: 128 threads, id 1 or 2
__device__ __forceinline__ void barGroup(int id) {
    asm volatile("bar.sync %0, 128;" :: "r"(id) : "memory");
}

// ---------------- per-direction grid barrier (64 CTAs resident) --------------
__device__ __forceinline__ void gridBarrierDir(int dir, int nCta) {
    __threadfence();              // every thread's h-writes visible GPU-wide
    __syncthreads();
    if (threadIdx.x == 0) {
        volatile unsigned int* ep = &g_barEpoch2[dir];
        unsigned int e = *ep;
        if (atomicAdd(&g_barArrive2[dir], 1u) == (unsigned)(nCta - 1)) {
            g_barArrive2[dir] = 0u;
            __threadfence();
            *ep = e + 1u;
        } else {
            while (*ep == e) { __nanosleep(32); }
        }
        __threadfence();
    }
    __syncthreads();
}

// ---------------- SGEMM: C[M,N] = A[M,K] @ W[N,K]^T + (b1+b2)[N] -------------
// 128x128x8 tiles, 256 thr, 8x8 thread tile, fp32x2 packed FMA.
// blockIdx.z selects direction (fwd/bwd weight set + output slab).
__global__ __launch_bounds__(256) void sgemm_bias2(
    const float* __restrict__ A,
    const float* __restrict__ Wf, const float* __restrict__ b1f, const float* __restrict__ b2f,
    const float* __restrict__ Wb, const float* __restrict__ b1b, const float* __restrict__ b2b,
    float* __restrict__ Cbase, size_t dirStride, int M, int N, int K)
{
    int dirz = blockIdx.z;
    const float* W     = dirz ? Wb  : Wf;
    const float* bias1 = dirz ? b1b : b1f;
    const float* bias2 = dirz ? b2b : b2f;
    float* C = Cbase + (size_t)dirz * dirStride;

    __shared__ float As[2][8][128];
    __shared__ float Ws[2][8][128];
    int tid = threadIdx.x;
    int nBase = blockIdx.x * 128;
    int mBase = blockIdx.y * 128;

    int lr = tid >> 1;
    int lk = (tid & 1) * 4;
    const float* Ag = A + (size_t)(mBase + lr) * K + lk;
    const float* Wg = W + (size_t)(nBase + lr) * K + lk;

    {
        float4 a4 = *(const float4*)Ag;
        float4 w4 = *(const float4*)Wg;
        As[0][lk + 0][lr] = a4.x; As[0][lk + 1][lr] = a4.y;
        As[0][lk + 2][lr] = a4.z; As[0][lk + 3][lr] = a4.w;
        Ws[0][lk + 0][lr] = w4.x; Ws[0][lk + 1][lr] = w4.y;
        Ws[0][lk + 2][lr] = w4.z; Ws[0][lk + 3][lr] = w4.w;
    }
    __syncthreads();

    int ty = tid >> 4, tx = tid & 15;
    unsigned long long acc2[8][4];
    #pragma unroll
    for (int i = 0; i < 8; i++)
        #pragma unroll
        for (int j = 0; j < 4; j++) acc2[i][j] = 0ull;   // two packed +0.0f

    int KT = K / 8;
    for (int kt = 0; kt < KT; ++kt) {
        int cu = kt & 1;
        float4 na, nw;
        bool more = (kt + 1 < KT);
        if (more) {
            na = *(const float4*)(Ag + (size_t)(kt + 1) * 8);
            nw = *(const float4*)(Wg + (size_t)(kt + 1) * 8);
        }
        #pragma unroll
        for (int k = 0; k < 8; k++) {
            float4 t0 = *(const float4*)&As[cu][k][ty * 8];
            float4 t1 = *(const float4*)&As[cu][k][ty * 8 + 4];
            float4 s0 = *(const float4*)&Ws[cu][k][tx * 8];
            float4 s1 = *(const float4*)&Ws[cu][k][tx * 8 + 4];
            unsigned long long w01 = pack2(s0.x, s0.y);
            unsigned long long w23 = pack2(s0.z, s0.w);
            unsigned long long w45 = pack2(s1.x, s1.y);
            unsigned long long w67 = pack2(s1.z, s1.w);
            float ar[8];
            ar[0] = t0.x; ar[1] = t0.y; ar[2] = t0.z; ar[3] = t0.w;
            ar[4] = t1.x; ar[5] = t1.y; ar[6] = t1.z; ar[7] = t1.w;
            #pragma unroll
            for (int i = 0; i < 8; i++) {
                unsigned long long ai = pack2(ar[i], ar[i]);
                ffma2(acc2[i][0], ai, w01);
                ffma2(acc2[i][1], ai, w23);
                ffma2(acc2[i][2], ai, w45);
                ffma2(acc2[i][3], ai, w67);
            }
        }
        if (more) {
            int nx = cu ^ 1;
            As[nx][lk + 0][lr] = na.x; As[nx][lk + 1][lr] = na.y;
            As[nx][lk + 2][lr] = na.z; As[nx][lk + 3][lr] = na.w;
            Ws[nx][lk + 0][lr] = nw.x; Ws[nx][lk + 1][lr] = nw.y;
            Ws[nx][lk + 2][lr] = nw.z; Ws[nx][lk + 3][lr] = nw.w;
        }
        __syncthreads();
    }

    float bs[8];
    #pragma unroll
    for (int j = 0; j < 8; j++) {
        int n = nBase + tx * 8 + j;
        bs[j] = bias1[n] + bias2[n];
    }
    #pragma unroll
    for (int i = 0; i < 8; i++) {
        int m = mBase + ty * 8 + i;
        float2 p0 = unpack2(acc2[i][0]);
        float2 p1 = unpack2(acc2[i][1]);
        float2 p2 = unpack2(acc2[i][2]);
        float2 p3 = unpack2(acc2[i][3]);
        float4 o0, o1;
        o0.x = p0.x + bs[0]; o0.y = p0.y + bs[1];
        o0.z = p1.x + bs[2]; o0.w = p1.y + bs[3];
        o1.x = p2.x + bs[4]; o1.y = p2.y + bs[5];
        o1.z = p3.x + bs[6]; o1.w = p3.y + bs[7];
        *(float4*)&C[(size_t)m * N + nBase + tx * 8 + 0] = o0;
        *(float4*)&C[(size_t)m * N + nBase + tx * 8 + 4] = o1;
    }
}

// ---------------- persistent BiLSTM layer ------------------------------------
// 128 CTAs x 256 thr: dir = blk>>6, part = blk&63 -> CTA owns 6 h-dims
// (24 gate rows). W_hh slice SMEM-resident pre-packed (w,w); h via L2
// (__ldcg) + per-dir grid barrier. K split over two 128-thread groups with
// group-local staging (named barriers) and 2-chunk load/GEMV pipelining.
__global__ __launch_bounds__(256) void lstm_layer(
    const float* __restrict__ pre,    // [2][B][T][1536]
    const float* __restrict__ whhF,   // [1536][384]
    const float* __restrict__ whhB,
    float* __restrict__ outL)         // [B][T][768]
{
    extern __shared__ unsigned long long smu[];
    unsigned long long* Wtp = smu;                    // [384*24] packed (w,w)
    float* hs  = (float*)(smu + 384 * 24);            // [384*64] h_prev k-major
    float* gp0 = hs + 384 * 64;                       // [24*64] partial (k lo)
    float* gp1 = gp0 + 24 * 64;                       // [24*64] partial (k hi)
    float* cst = gp1 + 24 * 64;                       // [6*64]  cell state

    int tid  = threadIdx.x;
    int dir  = blockIdx.x >> 6;
    int part = blockIdx.x & 63;
    int jbase = part * 6;
    const float* whh  = dir ? whhB : whhF;
    const float* preD = pre + (size_t)dir * BB * TT * GG;

    // load W slice: Wtp[k*24 + r] = pack(w,w), w = whh[(r/6)*384 + jbase + r%6][k]
    for (int idx = tid; idx < 24 * 384; idx += 256) {
        int r = idx / 384, k = idx % 384;
        int grow = (r / 6) * 384 + jbase + (r % 6);
        float w = whh[(size_t)grow * 384 + k];
        Wtp[k * 24 + r] = pack2(w, w);
    }
    for (int idx = tid; idx < 6 * 64; idx += 256) cst[idx] = 0.f;
    __syncthreads();

    int kh = tid >> 7;              // K half: 0 -> [0,192), 1 -> [192,384)
    int t2 = tid & 127;
    int rg = t2 >> 4, cg = t2 & 15;
    int r0 = rg * 3, b0 = cg * 4;
    int gate = r0 / 6;
    int rjo = gate * 384 + jbase + (r0 % 6);
    int kbeg = kh * 192;
    float* gpart = kh ? gp1 : gp0;
    int barid = kh + 1;
    float4* hsg = (float4*)hs + kh * 3072;            // this group's h half

    for (int t = 0; t < TT; ++t) {
        int tq = dir ? (TT - 1 - t) : t;

        // prefetch pre (only half 0 adds it); latency hidden by GEMV
        float pv[3][4];
        if (kh == 0) {
            #pragma unroll
            for (int j = 0; j < 4; j++) {
                const float* pb = preD + ((size_t)(b0 + j) * TT + tq) * GG + rjo;
                pv[0][j] = pb[0]; pv[1][j] = pb[1]; pv[2][j] = pb[2];
            }
        }

        unsigned long long acc2[3][2];
        #pragma unroll
        for (int i = 0; i < 3; i++) { acc2[i][0] = 0ull; acc2[i][1] = 0ull; }

        if (t > 0) {
            // group-local staging of this group's h half (disjoint across groups)
            const float4* srcg = (const float4*)(g_hstate +
                (size_t)((((t & 1) ^ 1) * 2 + dir)) * HH * BB) + kh * 3072;

            // chunk 0: k in [kbeg, kbeg+96) -> float4 [0,1536) of this half
            float4 v0[12];
            #pragma unroll
            for (int it = 0; it < 12; ++it) v0[it] = __ldcg(srcg + t2 + 128 * it);
            #pragma unroll
            for (int it = 0; it < 12; ++it) hsg[t2 + 128 * it] = v0[it];
            // issue chunk 1 loads early (hidden under GEMV chunk 0)
            float4 v1[12];
            #pragma unroll
            for (int it = 0; it < 12; ++it) v1[it] = __ldcg(srcg + 1536 + t2 + 128 * it);
            barGroup(barid);

            // GEMV chunk 0: 3 rows x 4 batch over k in [kbeg, kbeg+96)
            #pragma unroll 4
            for (int k = kbeg; k < kbeg + 96; k++) {
                float4 hv = *(const float4*)&hs[k * 64 + b0];
                unsigned long long h01 = pack2(hv.x, hv.y);
                unsigned long long h23 = pack2(hv.z, hv.w);
                unsigned long long w0 = Wtp[k * 24 + r0 + 0];
                unsigned long long w1 = Wtp[k * 24 + r0 + 1];
                unsigned long long w2 = Wtp[k * 24 + r0 + 2];
                ffma2(acc2[0][0], w0, h01); ffma2(acc2[0][1], w0, h23);
                ffma2(acc2[1][0], w1, h01); ffma2(acc2[1][1], w1, h23);
                ffma2(acc2[2][0], w2, h01); ffma2(acc2[2][1], w2, h23);
            }

            #pragma unroll
            for (int it = 0; it < 12; ++it) hsg[1536 + t2 + 128 * it] = v1[it];
            barGroup(barid);

            // GEMV chunk 1: k in [kbeg+96, kbeg+192)
            #pragma unroll 4
            for (int k = kbeg + 96; k < kbeg + 192; k++) {
                float4 hv = *(const float4*)&hs[k * 64 + b0];
                unsigned long long h01 = pack2(hv.x, hv.y);
                unsigned long long h23 = pack2(hv.z, hv.w);
                unsigned long long w0 = Wtp[k * 24 + r0 + 0];
                unsigned long long w1 = Wtp[k * 24 + r0 + 1];
                unsigned long long w2 = Wtp[k * 24 + r0 + 2];
                ffma2(acc2[0][0], w0, h01); ffma2(acc2[0][1], w0, h23);
                ffma2(acc2[1][0], w1, h01); ffma2(acc2[1][1], w1, h23);
                ffma2(acc2[2][0], w2, h01); ffma2(acc2[2][1], w2, h23);
            }
        }

        #pragma unroll
        for (int i = 0; i < 3; i++) {
            float2 p0 = unpack2(acc2[i][0]);
            float2 p1 = unpack2(acc2[i][1]);
            float* gw = &gpart[(r0 + i) * 64 + b0];
            if (kh == 0) {
                gw[0] = p0.x + pv[i][0]; gw[1] = p0.y + pv[i][1];
                gw[2] = p1.x + pv[i][2]; gw[3] = p1.y + pv[i][3];
            } else {
                gw[0] = p0.x; gw[1] = p0.y; gw[2] = p1.x; gw[3] = p1.y;
            }
        }
        __syncthreads();

        // gate math: 6 h-dims x 64 batch
        int nxtoff = ((t & 1) * 2 + dir) * HH * BB;
        for (int idx = tid; idx < 384; idx += 256) {
            int j = idx >> 6, b = idx & 63;
            float gi = gp0[(0  + j) * 64 + b] + gp1[(0  + j) * 64 + b];
            float gf = gp0[(6  + j) * 64 + b] + gp1[(6  + j) * 64 + b];
            float gc = gp0[(12 + j) * 64 + b] + gp1[(12 + j) * 64 + b];
            float go = gp0[(18 + j) * 64 + b] + gp1[(18 + j) * 64 + b];
            float iv = 1.f / (1.f + expf(-gi));
            float fv = 1.f / (1.f + expf(-gf));
            float cv = tanhf(gc);
            float ov = 1.f / (1.f + expf(-go));
            float c = fv * cst[j * 64 + b] + iv * cv;
            cst[j * 64 + b] = c;
            float h = ov * tanhf(c);
            g_hstate[nxtoff + (jbase + j) * 64 + b] = h;
            outL[((size_t)b * TT + tq) * (2 * HH) + dir * HH + jbase + j] = h;
        }
        gridBarrierDir(dir, 64);
    }
}

// ---------------- FC: feats = h2 @ fc_w^T + fc_b (warp per token) ------------
__global__ __launch_bounds__(256) void fc_feats(
    const float* __restrict__ h2, const float* __restrict__ fw,
    const float* __restrict__ fb, float* __restrict__ feats)
{
    int warp = blockIdx.x * 8 + (threadIdx.x >> 5);
    int lane = threadIdx.x & 31;
    if (warp >= BB * TT) return;

    float hv[24];
    const float* hrow = h2 + (size_t)warp * DD;
    #pragma unroll
    for (int i = 0; i < 24; i++) hv[i] = hrow[lane + 32 * i];

    for (int n = 0; n < NTAG; n++) {
        const float* w = fw + n * DD;
        float s = 0.f;
        #pragma unroll
        for (int i = 0; i < 24; i++) s += hv[i] * __ldg(&w[lane + 32 * i]);
        #pragma unroll
        for (int o = 16; o; o >>= 1) s += __shfl_xor_sync(0xffffffffu, s, o);
        if (lane == 0) feats[(size_t)warp * NTAG + n] = s + fb[n];
    }
}

// ---------------- Viterbi: one CTA per batch row -----------------------------
__global__ __launch_bounds__(128) void viterbi(
    const float* __restrict__ feats, const float* __restrict__ trans,
    float* __restrict__ out, int out_size)
{
    __shared__ float tr[NTAG * 32];
    __shared__ float ld[32];
    __shared__ float nld[32];
    __shared__ unsigned char psi[(TT - 1) * NTAG];
    extern __shared__ float sfeat[];   // [TT*NTAG]

    int b = blockIdx.x, tid = threadIdx.x;
    const float* fbr = feats + (size_t)b * TT * NTAG;
    for (int i = tid; i < TT * NTAG; i += 128) sfeat[i] = fbr[i];
    for (int i = tid; i < NTAG * NTAG; i += 128)
        tr[(i / NTAG) * 32 + (i % NTAG)] = trans[i];
    if (tid < 32) ld[tid] = -10000.0f;   // faithful: feats[:,0] never added
    __syncthreads();

    if (tid < 32) {
        int n = tid;
        for (int t = 1; t < TT; t++) {
            float best = -3.4e38f; int arg = 0;
            if (n < NTAG) {
                #pragma unroll 6
                for (int p = 0; p < NTAG; p++) {
                    float v = tr[n * 32 + p] + ld[p];
                    if (v > best) { best = v; arg = p; }   // first-max (jnp.argmax)
                }
                nld[n] = best + sfeat[t * NTAG + n];
                psi[(t - 1) * NTAG + n] = (unsigned char)arg;
            }
            __syncwarp();
            if (n < NTAG) ld[n] = nld[n];
            __syncwarp();
        }
        if (n == 0) {
            float best = ld[0]; int last = 0;
            for (int p = 1; p < NTAG; p++)
                if (ld[p] > best) { best = ld[p]; last = p; }

            float* score_out = nullptr; float* path_out = nullptr;
            if (out_size >= 64 + BB * TT) { score_out = out; path_out = out + 64; }
            else if (out_size == BB * TT) { path_out = out; }
            else { score_out = out; }

            if (score_out) score_out[b] = best;
            if (path_out) {
                int tag = last;
                path_out[(size_t)b * TT + TT - 1] = (float)tag;
                for (int t = TT - 2; t >= 0; t--) {
                    tag = psi[t * NTAG + tag];
                    path_out[(size_t)b * TT + t] = (float)tag;
                }
            }
        }
    }
}

// ---------------- launch -----------------------------------------------------
extern "C" void kernel_launch(void* const* d_in, const int* in_sizes, int n_in,
                              void* d_out, int out_size) {
    const float* embeds   = (const float*)d_in[0];
    const float* w_hh_l0f = (const float*)d_in[5];
    const float* w_hh_l0b = (const float*)d_in[9];
    const float* w_hh_l1f = (const float*)d_in[13];
    const float* w_hh_l1b = (const float*)d_in[17];

    float *pre, *h1, *h2, *feats;
    cudaGetSymbolAddress((void**)&pre,   g_pre);
    cudaGetSymbolAddress((void**)&h1,    g_h1);
    cudaGetSymbolAddress((void**)&h2,    g_h2);
    cudaGetSymbolAddress((void**)&feats, g_feats);

    const int LSMEM = 384 * 24 * 8 + (384 * 64 + 24 * 64 * 2 + 6 * 64) * 4; // 185856
    const int VSMEM = TT * NTAG * 4;                                        // 61440
    cudaFuncSetAttribute(lstm_layer, cudaFuncAttributeMaxDynamicSharedMemorySize, LSMEM);
    cudaFuncSetAttribute(viterbi,    cudaFuncAttributeMaxDynamicSharedMemorySize, VSMEM);

    const int M = BB * TT;
    dim3 gg(GG / 128, M / 128, 2);
    size_t dirStride = (size_t)BB * TT * GG;

    // Layer 0 (fwd+bwd fused in one launch via blockIdx.z)
    sgemm_bias2<<<gg, 256>>>(embeds,
        (const float*)d_in[4],  (const float*)d_in[6],  (const float*)d_in[7],
        (const float*)d_in[8],  (const float*)d_in[10], (const float*)d_in[11],
        pre, dirStride, M, GG, DD);
    lstm_layer<<<NCTA_LSTM, 256, LSMEM>>>(pre, w_hh_l0f, w_hh_l0b, h1);

    // Layer 1
    sgemm_bias2<<<gg, 256>>>(h1,
        (const float*)d_in[12], (const float*)d_in[14], (const float*)d_in[15],
        (const float*)d_in[16], (const float*)d_in[18], (const float*)d_in[19],
        pre, dirStride, M, GG, DD);
    lstm_layer<<<NCTA_LSTM, 256, LSMEM>>>(pre, w_hh_l1f, w_hh_l1b, h2);

    // FC + Viterbi
    fc_feats<<<(M + 7) / 8, 256>>>(h2, (const float*)d_in[2], (const float*)d_in[3], feats);
    viterbi<<<BB, 128, VSMEM>>>(feats, (const float*)d_in[1], (float*)d_out, out_size);
}